// round 1
// baseline (speedup 1.0000x reference)
#include <cuda_runtime.h>
#include <cuda_bf16.h>

// Problem constants
#define BB 8
#define CC 64
#define NN 4096
#define KK 32
#define HH 4
#define DD 16
#define ROWS (BB*NN)          // 32768
#define FULLMASK 0xffffffffu

// -------------------- device scratch (no allocations allowed) --------------------
__device__ float g_feat[ROWS*CC];   // (B,N,C) fp32
__device__ float g_sqn[ROWS];       // squared norms
__device__ int   g_knn[ROWS*KK];    // top-K indices (in-batch n)
__device__ float g_f0[ROWS*CC];     // feat + attention out
__device__ float g_f2[ROWS*CC];     // f1 + ff (pre-BN2)
__device__ float g_psum[128*CC];
__device__ float g_psq[128*CC];
__device__ float g_mu[CC];
__device__ float g_rs[CC];

// -------------------- warp helpers --------------------
__device__ __forceinline__ float warp_min32(float v){
#pragma unroll
  for (int o=16;o>0;o>>=1) v = fminf(v, __shfl_xor_sync(FULLMASK, v, o));
  return v;
}
__device__ __forceinline__ float warp_max32(float v){
#pragma unroll
  for (int o=16;o>0;o>>=1) v = fmaxf(v, __shfl_xor_sync(FULLMASK, v, o));
  return v;
}
__device__ __forceinline__ float warp_sum32(float v){
#pragma unroll
  for (int o=16;o>0;o>>=1) v += __shfl_xor_sync(FULLMASK, v, o);
  return v;
}

// -------------------- 1. transpose x (B,C,N) -> feat (B,N,C) --------------------
__global__ void transpose_kernel(const float* __restrict__ x){
  __shared__ float tile[32][33];
  int b  = blockIdx.z;
  int c0 = blockIdx.y * 32;
  int n0 = blockIdx.x * 32;
  int tx = threadIdx.x, ty = threadIdx.y;   // (32,8)
  const float* xb = x + (size_t)b*CC*NN;
#pragma unroll
  for (int i = 0; i < 32; i += 8)
    tile[ty+i][tx] = xb[(size_t)(c0+ty+i)*NN + n0 + tx];
  __syncthreads();
  float* fb = g_feat + (size_t)b*NN*CC;
#pragma unroll
  for (int i = 0; i < 32; i += 8)
    fb[(size_t)(n0+ty+i)*CC + c0 + tx] = tile[tx][ty+i];
}

// -------------------- 2. squared norms --------------------
__global__ void sqnorm_kernel(){
  int row = blockIdx.x*blockDim.x + threadIdx.x;
  if (row >= ROWS) return;
  const float4* f = (const float4*)(g_feat + (size_t)row*CC);
  float s = 0.f;
#pragma unroll
  for (int i=0;i<16;i++){ float4 v=f[i]; s += v.x*v.x+v.y*v.y+v.z*v.z+v.w*v.w; }
  g_sqn[row] = s;
}

// -------------------- 3. KNN: tiled Gram + online warp top-32 --------------------
// Block 256 thr = 8 warps. Block owns 32 rows (4 per warp), streams m in tiles of 128.
__global__ __launch_bounds__(256) void knn_kernel(){
  __shared__ float fnT[64][32];   // [c][r]
  __shared__ float fmT[64][128];  // [c][m]
  __shared__ float ssq[128];
  int b = blockIdx.y;
  int nbase = blockIdx.x * 32;
  const float* fb = g_feat + (size_t)b*NN*CC;
  int tid = threadIdx.x;
  int lane = tid & 31, wid = tid >> 5;
  int r0 = wid * 4;

  // load fnT (32 rows) transposed, conflict-free stores (lanes vary r)
  {
    int r = tid & 31; int c4 = tid >> 5;      // c4 in 0..7
#pragma unroll
    for (int it = 0; it < 2; it++){
      int c = (c4 + it*8) * 4;
      float4 v = *(const float4*)(fb + (size_t)(nbase + r)*CC + c);
      fnT[c][r]=v.x; fnT[c+1][r]=v.y; fnT[c+2][r]=v.z; fnT[c+3][r]=v.w;
    }
  }

  float cur_val[4]; int cur_idx[4];
#pragma unroll
  for (int i=0;i<4;i++){ cur_val[i] = -3.4e38f; cur_idx[i] = 0; }

  for (int mbase = 0; mbase < NN; mbase += 128){
    __syncthreads();
    // load fmT (128 rows) transposed; lanes vary m -> conflict-free stores
    {
      int m = tid & 127; int c4b = tid >> 7;  // 0/1
#pragma unroll
      for (int it = 0; it < 8; it++){
        int c = (c4b + it*2) * 4;
        float4 v = *(const float4*)(fb + (size_t)(mbase + m)*CC + c);
        fmT[c][m]=v.x; fmT[c+1][m]=v.y; fmT[c+2][m]=v.z; fmT[c+3][m]=v.w;
      }
      if (tid < 128) ssq[tid] = g_sqn[(size_t)b*NN + mbase + tid];
    }
    __syncthreads();

    // 4x4 register tile of dots: rows r0..r0+3, cols lane*4..lane*4+3
    float acc[4][4];
#pragma unroll
    for (int i=0;i<4;i++)
#pragma unroll
      for (int j=0;j<4;j++) acc[i][j]=0.f;

#pragma unroll 8
    for (int c = 0; c < 64; c++){
      float4 fn = *(const float4*)(&fnT[c][r0]);        // warp-broadcast
      float4 fm = *(const float4*)(&fmT[c][lane*4]);    // conflict-free
      acc[0][0]+=fn.x*fm.x; acc[0][1]+=fn.x*fm.y; acc[0][2]+=fn.x*fm.z; acc[0][3]+=fn.x*fm.w;
      acc[1][0]+=fn.y*fm.x; acc[1][1]+=fn.y*fm.y; acc[1][2]+=fn.y*fm.z; acc[1][3]+=fn.y*fm.w;
      acc[2][0]+=fn.z*fm.x; acc[2][1]+=fn.z*fm.y; acc[2][2]+=fn.z*fm.z; acc[2][3]+=fn.z*fm.w;
      acc[3][0]+=fn.w*fm.x; acc[3][1]+=fn.w*fm.y; acc[3][2]+=fn.w*fm.z; acc[3][3]+=fn.w*fm.w;
    }

    // online top-32 merge (lane = slot). score = 2*dot - sq[m] (row-constant dropped)
#pragma unroll
    for (int i=0;i<4;i++){
      float thr = warp_min32(cur_val[i]);
#pragma unroll
      for (int j=0;j<4;j++){
        float v = 2.0f*acc[i][j] - ssq[lane*4+j];
        int   mi = mbase + lane*4 + j;
        unsigned mask = __ballot_sync(FULLMASK, v > thr);
        while (mask){
          int src = __ffs(mask) - 1; mask &= mask - 1;
          float cv = __shfl_sync(FULLMASK, v,  src);
          int   ci = __shfl_sync(FULLMASK, mi, src);
          // warp argmin of cur_val[i]
          float mv = cur_val[i]; int ml = lane;
#pragma unroll
          for (int off=16; off>0; off>>=1){
            float ov = __shfl_down_sync(FULLMASK, mv, off);
            int   ol = __shfl_down_sync(FULLMASK, ml, off);
            if (ov < mv){ mv = ov; ml = ol; }
          }
          mv = __shfl_sync(FULLMASK, mv, 0);
          ml = __shfl_sync(FULLMASK, ml, 0);
          if (cv > mv){
            if (lane == ml){ cur_val[i] = cv; cur_idx[i] = ci; }
            thr = warp_min32(cur_val[i]);
          }
        }
      }
    }
  }
#pragma unroll
  for (int i=0;i<4;i++)
    g_knn[((size_t)b*NN + nbase + r0 + i)*KK + lane] = cur_idx[i];
}

// -------------------- 4. fused gather/diff + QKV + attention --------------------
// Block 128 thr = 4 warps, each warp does 4 rows serially. smem: 3 transposed
// weights (12288 f) + per-warp diff[c][k] (2048) + fn (64) + energies (128).
__device__ __forceinline__ void proj8(const float* __restrict__ wT,
                                      const float* __restrict__ sdiff,
                                      int lane, int g, float a0[8], float a1[8]){
#pragma unroll
  for (int t=0;t<8;t++){ a0[t]=0.f; a1[t]=0.f; }
#pragma unroll
  for (int c=0;c<64;c++){
    float w0 = wT[c*64 + lane];
    float w1 = wT[c*64 + lane + 32];
    float4 d0 = *(const float4*)(sdiff + c*32 + g*8);
    float4 d1 = *(const float4*)(sdiff + c*32 + g*8 + 4);
    a0[0]+=d0.x*w0; a0[1]+=d0.y*w0; a0[2]+=d0.z*w0; a0[3]+=d0.w*w0;
    a0[4]+=d1.x*w0; a0[5]+=d1.y*w0; a0[6]+=d1.z*w0; a0[7]+=d1.w*w0;
    a1[0]+=d0.x*w1; a1[1]+=d0.y*w1; a1[2]+=d0.z*w1; a1[3]+=d0.w*w1;
    a1[4]+=d1.x*w1; a1[5]+=d1.y*w1; a1[6]+=d1.z*w1; a1[7]+=d1.w*w1;
  }
}

__global__ __launch_bounds__(128) void attn_kernel(const float* __restrict__ wq,
                                                   const float* __restrict__ wk,
                                                   const float* __restrict__ wv){
  extern __shared__ float sm[];
  float* wqT = sm;            // [c][o] 64x64
  float* wkT = sm + 4096;
  float* wvT = sm + 8192;
  int tid = threadIdx.x;
  int lane = tid & 31, wid = tid >> 5;
  float* wsm   = sm + 12288 + wid*2240;
  float* sdiff = wsm;         // [c][k] 64x32
  float* sfn   = wsm + 2048;  // 64
  float* se    = wsm + 2112;  // [h][k] 4x32

  // load & transpose weights: lanes vary o -> conflict-free stores
  {
    int o = tid & 63, half = tid >> 6;
#pragma unroll
    for (int it = 0; it < 8; it++){
      int c = (half + 2*it) * 4;
      float4 a = *(const float4*)(wq + o*64 + c);
      wqT[c*64+o]=a.x; wqT[(c+1)*64+o]=a.y; wqT[(c+2)*64+o]=a.z; wqT[(c+3)*64+o]=a.w;
      float4 bk = *(const float4*)(wk + o*64 + c);
      wkT[c*64+o]=bk.x; wkT[(c+1)*64+o]=bk.y; wkT[(c+2)*64+o]=bk.z; wkT[(c+3)*64+o]=bk.w;
      float4 bv = *(const float4*)(wv + o*64 + c);
      wvT[c*64+o]=bv.x; wvT[(c+1)*64+o]=bv.y; wvT[(c+2)*64+o]=bv.z; wvT[(c+3)*64+o]=bv.w;
    }
  }
  __syncthreads();

  int rowbase = blockIdx.x * 16;
  int b = rowbase >> 12;
  const float* fb = g_feat + (size_t)b*NN*CC;
  int hq = lane >> 4;

  for (int rr = 0; rr < 4; rr++){
    int row = rowbase + wid*4 + rr;
    sfn[lane]      = g_feat[(size_t)row*CC + lane];
    sfn[lane + 32] = g_feat[(size_t)row*CC + lane + 32];
    __syncwarp();

    // gather neighbor row (lane = k), build diff in [c][k] layout
    int nbr = g_knn[(size_t)row*KK + lane];
    const float* frow = fb + (size_t)nbr*CC;
#pragma unroll
    for (int c4 = 0; c4 < 16; c4++){
      float4 v = *(const float4*)(frow + c4*4);
      int c = c4*4;
      sdiff[(c  )*32 + lane] = v.x - sfn[c  ];
      sdiff[(c+1)*32 + lane] = v.y - sfn[c+1];
      sdiff[(c+2)*32 + lane] = v.z - sfn[c+2];
      sdiff[(c+3)*32 + lane] = v.w - sfn[c+3];
    }
    __syncwarp();

    // q projection (lane owns o=lane and o=lane+32)
    float q0 = 0.f, q1 = 0.f;
#pragma unroll
    for (int c = 0; c < 64; c++){
      float f = sfn[c];
      q0 += f * wqT[c*64 + lane];
      q1 += f * wqT[c*64 + lane + 32];
    }

    // k projection (8 neighbors per group) + energies
#pragma unroll
    for (int g = 0; g < 4; g++){
      float a0[8], a1[8];
      proj8(wkT, sdiff, lane, g, a0, a1);
#pragma unroll
      for (int t = 0; t < 8; t++){
        float p0 = q0*a0[t], p1 = q1*a1[t];
#pragma unroll
        for (int off = 8; off > 0; off >>= 1){
          p0 += __shfl_xor_sync(FULLMASK, p0, off);
          p1 += __shfl_xor_sync(FULLMASK, p1, off);
        }
        if (!(lane & 15)){
          se[ hq   *32 + g*8 + t] = p0 * 0.25f;   // 1/sqrt(D)
          se[(hq+2)*32 + g*8 + t] = p1 * 0.25f;
        }
      }
    }
    __syncwarp();

    // softmax over K per head (lane = k)
#pragma unroll
    for (int h = 0; h < 4; h++){
      float e  = se[h*32 + lane];
      float mx = warp_max32(e);
      float ex = __expf(e - mx);
      float s  = warp_sum32(ex);
      se[h*32 + lane] = ex / s;
    }
    __syncwarp();

    // v projection + weighted sum
    float o0 = 0.f, o1 = 0.f;
#pragma unroll
    for (int g = 0; g < 4; g++){
      float a0[8], a1[8];
      proj8(wvT, sdiff, lane, g, a0, a1);
#pragma unroll
      for (int t = 0; t < 8; t++){
        o0 += se[ hq   *32 + g*8 + t] * a0[t];
        o1 += se[(hq+2)*32 + g*8 + t] * a1[t];
      }
    }
    g_f0[(size_t)row*CC + lane]      = sfn[lane]      + o0;
    g_f0[(size_t)row*CC + lane + 32] = sfn[lane + 32] + o1;
    __syncwarp();
  }
}

// -------------------- 5. BN stats (deterministic two-stage) --------------------
__global__ __launch_bounds__(256) void bn_stats_kernel(int which){
  const float* f = which ? g_f2 : g_f0;
  __shared__ float s1[256], s2[256];
  int c = threadIdx.x & 63, g = threadIdx.x >> 6;
  int rowbase = blockIdx.x * 256;
  float s = 0.f, q = 0.f;
  for (int r = g; r < 256; r += 4){
    float v = f[(size_t)(rowbase + r)*CC + c];
    s += v; q += v*v;
  }
  s1[threadIdx.x] = s; s2[threadIdx.x] = q;
  __syncthreads();
  if (threadIdx.x < 64){
    s = s1[c] + s1[c+64] + s1[c+128] + s1[c+192];
    q = s2[c] + s2[c+64] + s2[c+128] + s2[c+192];
    g_psum[blockIdx.x*64 + c] = s;
    g_psq [blockIdx.x*64 + c] = q;
  }
}

__global__ void bn_finalize_kernel(){
  int c = threadIdx.x;  // 64 threads
  float s = 0.f, q = 0.f;
  for (int i = 0; i < 128; i++){ s += g_psum[i*64 + c]; q += g_psq[i*64 + c]; }
  float m   = s * (1.f/32768.f);
  float var = q * (1.f/32768.f) - m*m;
  g_mu[c] = m;
  g_rs[c] = rsqrtf(var + 1e-5f);
}

// -------------------- 6. BN1-normalize + MLP + residual --------------------
#define MLP_ROWS 64
__global__ __launch_bounds__(256) void mlp_kernel(const float* __restrict__ w1,
                                                  const float* __restrict__ w2,
                                                  const float* __restrict__ g1,
                                                  const float* __restrict__ b1){
  extern __shared__ float sm[];
  float* w1T   = sm;              // [c][o] 64x256
  float* w2T   = sm + 16384;      // [o][c] 256x64
  float* sf1   = sm + 32768;      // 64
  float* shid  = sf1 + 64;        // 256
  float* spart = shid + 256;      // 256
  __shared__ float ssc[64], ssh[64];
  int tid = threadIdx.x;

  // transpose loads (lanes vary the contiguous smem index -> conflict-free)
  {
    int o = tid;
#pragma unroll
    for (int c4 = 0; c4 < 16; c4++){
      float4 v = *(const float4*)(w1 + o*64 + c4*4);
      int c = c4*4;
      w1T[c*256+o]=v.x; w1T[(c+1)*256+o]=v.y; w1T[(c+2)*256+o]=v.z; w1T[(c+3)*256+o]=v.w;
    }
    int c = tid & 63, o4b = tid >> 6;
#pragma unroll
    for (int it = 0; it < 16; it++){
      int o2 = (o4b + 4*it) * 4;
      float4 v = *(const float4*)(w2 + c*256 + o2);
      w2T[o2*64+c]=v.x; w2T[(o2+1)*64+c]=v.y; w2T[(o2+2)*64+c]=v.z; w2T[(o2+3)*64+c]=v.w;
    }
  }
  if (tid < 64){
    float r = g_rs[tid] * g1[tid];
    ssc[tid] = r;
    ssh[tid] = b1[tid] - g_mu[tid]*r;
  }
  __syncthreads();

  int rowbase = blockIdx.x * MLP_ROWS;
  for (int r = 0; r < MLP_ROWS; r++){
    int row = rowbase + r;
    if (tid < 64) sf1[tid] = g_f0[(size_t)row*CC + tid]*ssc[tid] + ssh[tid];
    __syncthreads();
    // layer 1: thread = output o
    float h = 0.f;
#pragma unroll
    for (int c = 0; c < 64; c++) h += sf1[c] * w1T[c*256 + tid];
    h = (h > 0.f) ? h : 0.2f*h;     // LeakyReLU(0.2)
    shid[tid] = h;
    __syncthreads();
    // layer 2: 4 partial groups per output channel
    float p = 0.f;
    int c = tid & 63, part = tid >> 6;
#pragma unroll
    for (int oo = 0; oo < 64; oo++){
      int o = part*64 + oo;
      p += shid[o] * w2T[o*64 + c];
    }
    spart[tid] = p;
    __syncthreads();
    if (tid < 64){
      float ff = spart[tid] + spart[tid+64] + spart[tid+128] + spart[tid+192];
      g_f2[(size_t)row*CC + tid] = sf1[tid] + ff;
    }
    __syncthreads();
  }
}

// -------------------- 7. BN2-normalize + transpose to (B,C,N) --------------------
__global__ void out_kernel(const float* __restrict__ g2, const float* __restrict__ b2,
                           float* __restrict__ out){
  __shared__ float tile[32][33];
  int b  = blockIdx.z;
  int c0 = blockIdx.y * 32;
  int n0 = blockIdx.x * 32;
  int tx = threadIdx.x, ty = threadIdx.y;
  const float* fb = g_f2 + (size_t)b*NN*CC;
#pragma unroll
  for (int i = 0; i < 32; i += 8)
    tile[ty+i][tx] = fb[(size_t)(n0+ty+i)*CC + c0 + tx];
  __syncthreads();
#pragma unroll
  for (int i = 0; i < 32; i += 8){
    int c = c0 + ty + i;
    float sc = g_rs[c]*g2[c];
    float sh = b2[c] - g_mu[c]*sc;
    out[((size_t)b*CC + c)*NN + n0 + tx] = tile[tx][ty+i]*sc + sh;
  }
}

// -------------------- launch --------------------
extern "C" void kernel_launch(void* const* d_in, const int* in_sizes, int n_in,
                              void* d_out, int out_size){
  (void)in_sizes; (void)n_in; (void)out_size;
  const float* x  = (const float*)d_in[0];
  const float* wq = (const float*)d_in[1];
  const float* wk = (const float*)d_in[2];
  const float* wv = (const float*)d_in[3];
  const float* w1 = (const float*)d_in[4];
  const float* w2 = (const float*)d_in[5];
  const float* g1 = (const float*)d_in[6];
  const float* b1 = (const float*)d_in[7];
  const float* g2 = (const float*)d_in[8];
  const float* b2 = (const float*)d_in[9];
  float* out = (float*)d_out;

  const int ATTN_SMEM = (12288 + 4*2240) * 4;                    // 84992 B
  const int MLP_SMEM  = (16384 + 16384 + 64 + 256 + 256) * 4;    // 133376 B
  cudaFuncSetAttribute(attn_kernel, cudaFuncAttributeMaxDynamicSharedMemorySize, ATTN_SMEM);
  cudaFuncSetAttribute(mlp_kernel,  cudaFuncAttributeMaxDynamicSharedMemorySize, MLP_SMEM);

  transpose_kernel<<<dim3(NN/32, CC/32, BB), dim3(32,8)>>>(x);
  sqnorm_kernel<<<ROWS/256, 256>>>();
  knn_kernel<<<dim3(NN/32, BB), 256>>>();
  attn_kernel<<<ROWS/16, 128, ATTN_SMEM>>>(wq, wk, wv);
  bn_stats_kernel<<<128, 256>>>(0);
  bn_finalize_kernel<<<1, 64>>>();
  mlp_kernel<<<ROWS/MLP_ROWS, 256, MLP_SMEM>>>(w1, w2, g1, b1);
  bn_stats_kernel<<<128, 256>>>(1);
  bn_finalize_kernel<<<1, 64>>>();
  out_kernel<<<dim3(NN/32, CC/32, BB), dim3(32,8)>>>(g2, b2, out);
}

// round 2
// speedup vs baseline: 1.5111x; 1.5111x over previous
#include <cuda_runtime.h>
#include <cuda_bf16.h>
#include <float.h>

// Problem constants
#define BB 8
#define CC 64
#define NN 4096
#define KK 32
#define HH 4
#define DD 16
#define ROWS (BB*NN)          // 32768
#define FULLMASK 0xffffffffu

// -------------------- device scratch --------------------
__device__ float g_feat[ROWS*CC];   // (B,N,C) fp32
__device__ float g_sqn[ROWS];       // squared norms
__device__ int   g_knn[ROWS*KK];    // top-K indices (in-batch n)
__device__ float g_f0[ROWS*CC];     // feat + attention out
__device__ float g_f2[ROWS*CC];     // f1 + ff (pre-BN2)
__device__ float g_psum[128*CC];
__device__ float g_psq[128*CC];
__device__ float g_mu[CC];
__device__ float g_rs[CC];

// -------------------- warp helpers --------------------
__device__ __forceinline__ float warp_min32(float v){
#pragma unroll
  for (int o=16;o>0;o>>=1) v = fminf(v, __shfl_xor_sync(FULLMASK, v, o));
  return v;
}
__device__ __forceinline__ float warp_max32(float v){
#pragma unroll
  for (int o=16;o>0;o>>=1) v = fmaxf(v, __shfl_xor_sync(FULLMASK, v, o));
  return v;
}
__device__ __forceinline__ float warp_sum32(float v){
#pragma unroll
  for (int o=16;o>0;o>>=1) v += __shfl_xor_sync(FULLMASK, v, o);
  return v;
}

// -------------------- 1. transpose x (B,C,N) -> feat (B,N,C) --------------------
__global__ void transpose_kernel(const float* __restrict__ x){
  __shared__ float tile[32][33];
  int b  = blockIdx.z;
  int c0 = blockIdx.y * 32;
  int n0 = blockIdx.x * 32;
  int tx = threadIdx.x, ty = threadIdx.y;   // (32,8)
  const float* xb = x + (size_t)b*CC*NN;
#pragma unroll
  for (int i = 0; i < 32; i += 8)
    tile[ty+i][tx] = xb[(size_t)(c0+ty+i)*NN + n0 + tx];
  __syncthreads();
  float* fb = g_feat + (size_t)b*NN*CC;
#pragma unroll
  for (int i = 0; i < 32; i += 8)
    fb[(size_t)(n0+ty+i)*CC + c0 + tx] = tile[tx][ty+i];
}

// -------------------- 2. squared norms --------------------
__global__ void sqnorm_kernel(){
  int row = blockIdx.x*blockDim.x + threadIdx.x;
  if (row >= ROWS) return;
  const float4* f = (const float4*)(g_feat + (size_t)row*CC);
  float s = 0.f;
#pragma unroll
  for (int i=0;i<16;i++){ float4 v=f[i]; s += v.x*v.x+v.y*v.y+v.z*v.z+v.w*v.w; }
  g_sqn[row] = s;
}

// -------------------- 3. KNN: tiled Gram + online warp top-32 --------------------
__global__ __launch_bounds__(256) void knn_kernel(){
  __shared__ float fnT[64][32];   // [c][r]
  __shared__ float fmT[64][128];  // [c][m]
  __shared__ float ssq[128];
  int b = blockIdx.y;
  int nbase = blockIdx.x * 32;
  const float* fb = g_feat + (size_t)b*NN*CC;
  int tid = threadIdx.x;
  int lane = tid & 31, wid = tid >> 5;
  int r0 = wid * 4;

  {
    int r = tid & 31; int c4 = tid >> 5;
#pragma unroll
    for (int it = 0; it < 2; it++){
      int c = (c4 + it*8) * 4;
      float4 v = *(const float4*)(fb + (size_t)(nbase + r)*CC + c);
      fnT[c][r]=v.x; fnT[c+1][r]=v.y; fnT[c+2][r]=v.z; fnT[c+3][r]=v.w;
    }
  }

  float cur_val[4]; int cur_idx[4]; float thr[4];
#pragma unroll
  for (int i=0;i<4;i++){ cur_val[i] = -FLT_MAX; cur_idx[i] = 0; thr[i] = -FLT_MAX; }

  for (int mbase = 0; mbase < NN; mbase += 128){
    __syncthreads();
    {
      int m = tid & 127; int c4b = tid >> 7;
#pragma unroll
      for (int it = 0; it < 8; it++){
        int c = (c4b + it*2) * 4;
        float4 v = *(const float4*)(fb + (size_t)(mbase + m)*CC + c);
        fmT[c][m]=v.x; fmT[c+1][m]=v.y; fmT[c+2][m]=v.z; fmT[c+3][m]=v.w;
      }
      if (tid < 128) ssq[tid] = g_sqn[(size_t)b*NN + mbase + tid];
    }
    __syncthreads();

    float acc[4][4];
#pragma unroll
    for (int i=0;i<4;i++)
#pragma unroll
      for (int j=0;j<4;j++) acc[i][j]=0.f;

#pragma unroll 8
    for (int c = 0; c < 64; c++){
      float4 fn = *(const float4*)(&fnT[c][r0]);
      float4 fm = *(const float4*)(&fmT[c][lane*4]);
      acc[0][0]+=fn.x*fm.x; acc[0][1]+=fn.x*fm.y; acc[0][2]+=fn.x*fm.z; acc[0][3]+=fn.x*fm.w;
      acc[1][0]+=fn.y*fm.x; acc[1][1]+=fn.y*fm.y; acc[1][2]+=fn.y*fm.z; acc[1][3]+=fn.y*fm.w;
      acc[2][0]+=fn.z*fm.x; acc[2][1]+=fn.z*fm.y; acc[2][2]+=fn.z*fm.z; acc[2][3]+=fn.z*fm.w;
      acc[3][0]+=fn.w*fm.x; acc[3][1]+=fn.w*fm.y; acc[3][2]+=fn.w*fm.z; acc[3][3]+=fn.w*fm.w;
    }

    float4 sq4 = *(const float4*)(&ssq[lane*4]);
#pragma unroll
    for (int i=0;i<4;i++){
      float v0 = 2.0f*acc[i][0] - sq4.x;
      float v1 = 2.0f*acc[i][1] - sq4.y;
      float v2 = 2.0f*acc[i][2] - sq4.z;
      float v3 = 2.0f*acc[i][3] - sq4.w;
      float vm = fmaxf(fmaxf(v0,v1), fmaxf(v2,v3));
      if (!__any_sync(FULLMASK, vm > thr[i])) continue;
      float vv[4] = {v0,v1,v2,v3};
#pragma unroll
      for (int j=0;j<4;j++){
        float v = vv[j];
        int   mi = mbase + lane*4 + j;
        unsigned mask = __ballot_sync(FULLMASK, v > thr[i]);
        while (mask){
          int src = __ffs(mask) - 1; mask &= mask - 1;
          float cv = __shfl_sync(FULLMASK, v,  src);
          int   ci = __shfl_sync(FULLMASK, mi, src);
          float mv = cur_val[i]; int ml = lane;
#pragma unroll
          for (int off=16; off>0; off>>=1){
            float ov = __shfl_down_sync(FULLMASK, mv, off);
            int   ol = __shfl_down_sync(FULLMASK, ml, off);
            if (ov < mv){ mv = ov; ml = ol; }
          }
          mv = __shfl_sync(FULLMASK, mv, 0);
          ml = __shfl_sync(FULLMASK, ml, 0);
          if (cv > mv){
            if (lane == ml){ cur_val[i] = cv; cur_idx[i] = ci; }
            thr[i] = warp_min32(cur_val[i]);
          }
        }
      }
    }
  }
#pragma unroll
  for (int i=0;i<4;i++)
    g_knn[((size_t)b*NN + nbase + r0 + i)*KK + lane] = cur_idx[i];
}

// -------------------- 4. factorized attention --------------------
// energy[h,k] = sum_c qk[h,c]*diff[c,k],  qk[h,c] = sum_{o in h} q[o] wk[o,c]
// out[o]     = sum_c wv[o,c]*wd[h(o),c],  wd[h,c] = sum_k attn[h,k] diff[c,k]
// Block 512 thr = 16 warps, 1 row per warp-iteration, 4 iterations.
#define AT_WARPS 16
#define AT_WBUF 2688            // floats per warp
#define DIFF_LD 68              // padded row stride for diff [k][68]

__global__ __launch_bounds__(512) void attn_kernel(const float* __restrict__ wq,
                                                   const float* __restrict__ wk,
                                                   const float* __restrict__ wv){
  extern __shared__ float sm[];
  float2* wq2 = (float2*)sm;          // [c][o32] pairs (o, o+32)   2048 f2
  float2* wv2 = wq2 + 2048;           // [c][o32]                   2048 f2
  float2* wk2 = wv2 + 2048;           // [o][c32] pairs (c, c+32)   2048 f2
  int tid = threadIdx.x;
  int lane = tid & 31, wid = tid >> 5;
  float* wb    = sm + 12288 + wid*AT_WBUF;
  float* sdiff = wb;                  // [k][68]  2176
  float* sfn   = wb + 2176;           // 64
  float* sq    = wb + 2240;           // 64
  float* sqk   = wb + 2304;           // [h][64]  256 (reused as swd)
  float* sattn = wb + 2560;           // [k][4]   128
  float* swd   = sqk;

  // pack weights into shared
  for (int idx = tid; idx < 2048; idx += 512){
    int cc = idx >> 5, oo = idx & 31;
    wq2[idx] = make_float2(wq[oo*64 + cc], wq[(oo+32)*64 + cc]);
    wv2[idx] = make_float2(wv[oo*64 + cc], wv[(oo+32)*64 + cc]);
    int o = idx >> 5, c = idx & 31;
    wk2[idx] = make_float2(wk[o*64 + c], wk[o*64 + c + 32]);
  }
  __syncthreads();

  int rowbase = blockIdx.x * (AT_WARPS*4);

  for (int rr = 0; rr < 4; rr++){
    int row = rowbase + wid*4 + rr;
    int b = row >> 12;

    // stage 1: load feature row
    sfn[lane]      = g_feat[(size_t)row*CC + lane];
    sfn[lane + 32] = g_feat[(size_t)row*CC + lane + 32];
    __syncwarp();

    // stage 2: gather neighbor (lane = k), diff in [k][68]
    {
      int nbr = g_knn[(size_t)row*KK + lane];
      const float4* frow = (const float4*)(g_feat + ((size_t)(b<<12) + nbr)*CC);
      float4* drow = (float4*)(sdiff + lane*DIFF_LD);
#pragma unroll
      for (int c4 = 0; c4 < 16; c4++){
        float4 v = frow[c4];
        float4 f = *(const float4*)(sfn + c4*4);
        drow[c4] = make_float4(v.x-f.x, v.y-f.y, v.z-f.z, v.w-f.w);
      }
    }

    // stage 3: q projection (lane owns o=lane, o=lane+32)
    {
      float q0 = 0.f, q1 = 0.f;
#pragma unroll
      for (int c4 = 0; c4 < 16; c4++){
        float4 f = *(const float4*)(sfn + c4*4);
        float2 w0 = wq2[(c4*4  )*32 + lane];
        float2 w1 = wq2[(c4*4+1)*32 + lane];
        float2 w2 = wq2[(c4*4+2)*32 + lane];
        float2 w3 = wq2[(c4*4+3)*32 + lane];
        q0 += f.x*w0.x + f.y*w1.x + f.z*w2.x + f.w*w3.x;
        q1 += f.x*w0.y + f.y*w1.y + f.z*w2.y + f.w*w3.y;
      }
      sq[lane] = q0; sq[lane+32] = q1;
    }
    __syncwarp();

    // stage 4: qk[h][c] (lane owns c=lane, c=lane+32)
    {
      float a[8];
#pragma unroll
      for (int t=0;t<8;t++) a[t]=0.f;
#pragma unroll
      for (int o = 0; o < 64; o++){
        int h = o >> 4;
        float qb = sq[o];
        float2 w = wk2[o*32 + lane];
        a[h*2  ] += qb*w.x;
        a[h*2+1] += qb*w.y;
      }
#pragma unroll
      for (int h=0;h<4;h++){
        sqk[h*64 + lane]      = a[h*2];
        sqk[h*64 + lane + 32] = a[h*2+1];
      }
    }
    __syncwarp();

    // stage 5: energies + softmax (lane = k)
    {
      float e0=0.f,e1=0.f,e2=0.f,e3=0.f;
      const float4* drow = (const float4*)(sdiff + lane*DIFF_LD);
#pragma unroll
      for (int c4 = 0; c4 < 16; c4++){
        float4 d = drow[c4];
        float4 k0 = *(const float4*)(sqk + 0*64 + c4*4);
        float4 k1 = *(const float4*)(sqk + 1*64 + c4*4);
        float4 k2 = *(const float4*)(sqk + 2*64 + c4*4);
        float4 k3 = *(const float4*)(sqk + 3*64 + c4*4);
        e0 += d.x*k0.x + d.y*k0.y + d.z*k0.z + d.w*k0.w;
        e1 += d.x*k1.x + d.y*k1.y + d.z*k1.z + d.w*k1.w;
        e2 += d.x*k2.x + d.y*k2.y + d.z*k2.z + d.w*k2.w;
        e3 += d.x*k3.x + d.y*k3.y + d.z*k3.z + d.w*k3.w;
      }
      float e[4] = {e0*0.25f, e1*0.25f, e2*0.25f, e3*0.25f};
      float a[4];
#pragma unroll
      for (int h=0;h<4;h++){
        float mx = warp_max32(e[h]);
        float ex = __expf(e[h]-mx);
        float s  = warp_sum32(ex);
        a[h] = ex / s;
      }
      *(float4*)(sattn + lane*4) = make_float4(a[0],a[1],a[2],a[3]);
    }
    __syncwarp();

    // stage 6: wd[h][c] (lane owns c=lane, c=lane+32)
    {
      float w[8];
#pragma unroll
      for (int t=0;t<8;t++) w[t]=0.f;
#pragma unroll
      for (int k = 0; k < 32; k++){
        float4 at = *(const float4*)(sattn + k*4);
        float d0 = sdiff[k*DIFF_LD + lane];
        float d1 = sdiff[k*DIFF_LD + lane + 32];
        w[0]+=at.x*d0; w[1]+=at.x*d1;
        w[2]+=at.y*d0; w[3]+=at.y*d1;
        w[4]+=at.z*d0; w[5]+=at.z*d1;
        w[6]+=at.w*d0; w[7]+=at.w*d1;
      }
      __syncwarp();      // sqk fully consumed (stage 5 done warp-wide)
#pragma unroll
      for (int h=0;h<4;h++){
        swd[h*64 + lane]      = w[h*2];
        swd[h*64 + lane + 32] = w[h*2+1];
      }
    }
    __syncwarp();

    // stage 7: output projection + residual (lane owns o=lane, o=lane+32)
    {
      int h0 = lane >> 4;          // head of o=lane (0/1); o+32 -> h0+2
      float o0 = 0.f, o1 = 0.f;
#pragma unroll
      for (int c4 = 0; c4 < 16; c4++){
        float4 d0 = *(const float4*)(swd + h0*64     + c4*4);
        float4 d1 = *(const float4*)(swd + (h0+2)*64 + c4*4);
        float2 w0 = wv2[(c4*4  )*32 + lane];
        float2 w1 = wv2[(c4*4+1)*32 + lane];
        float2 w2 = wv2[(c4*4+2)*32 + lane];
        float2 w3 = wv2[(c4*4+3)*32 + lane];
        o0 += d0.x*w0.x + d0.y*w1.x + d0.z*w2.x + d0.w*w3.x;
        o1 += d1.x*w0.y + d1.y*w1.y + d1.z*w2.y + d1.w*w3.y;
      }
      g_f0[(size_t)row*CC + lane]      = sfn[lane]      + o0;
      g_f0[(size_t)row*CC + lane + 32] = sfn[lane + 32] + o1;
    }
    __syncwarp();
  }
}

// -------------------- 5. BN stats (deterministic two-stage) --------------------
__global__ __launch_bounds__(256) void bn_stats_kernel(int which){
  const float* f = which ? g_f2 : g_f0;
  __shared__ float s1[256], s2[256];
  int c = threadIdx.x & 63, g = threadIdx.x >> 6;
  int rowbase = blockIdx.x * 256;
  float s = 0.f, q = 0.f;
  for (int r = g; r < 256; r += 4){
    float v = f[(size_t)(rowbase + r)*CC + c];
    s += v; q += v*v;
  }
  s1[threadIdx.x] = s; s2[threadIdx.x] = q;
  __syncthreads();
  if (threadIdx.x < 64){
    s = s1[c] + s1[c+64] + s1[c+128] + s1[c+192];
    q = s2[c] + s2[c+64] + s2[c+128] + s2[c+192];
    g_psum[blockIdx.x*64 + c] = s;
    g_psq [blockIdx.x*64 + c] = q;
  }
}

__global__ void bn_finalize_kernel(){
  int c = threadIdx.x;  // 64 threads
  float s = 0.f, q = 0.f;
  for (int i = 0; i < 128; i++){ s += g_psum[i*64 + c]; q += g_psq[i*64 + c]; }
  float m   = s * (1.f/32768.f);
  float var = q * (1.f/32768.f) - m*m;
  g_mu[c] = m;
  g_rs[c] = rsqrtf(var + 1e-5f);
}

// -------------------- 6. BN1-normalize + MLP + residual (4 rows/iter) ------------
__global__ __launch_bounds__(256) void mlp_kernel(const float* __restrict__ w1,
                                                  const float* __restrict__ w2,
                                                  const float* __restrict__ g1,
                                                  const float* __restrict__ b1){
  extern __shared__ float sm[];
  float* w1T   = sm;              // [c][o] 64x256
  float* w2T   = sm + 16384;      // [o][c] 256x64
  float* sf1T  = sm + 32768;      // [c][j] 64x4
  float* shT   = sm + 33024;      // [o][j] 256x4
  float* spart = sm + 34048;      // [(j*4+part)][c] 16x64
  __shared__ float ssc[64], ssh[64];
  int tid = threadIdx.x;

  {
    int o = tid;
#pragma unroll
    for (int c4 = 0; c4 < 16; c4++){
      float4 v = *(const float4*)(w1 + o*64 + c4*4);
      int c = c4*4;
      w1T[c*256+o]=v.x; w1T[(c+1)*256+o]=v.y; w1T[(c+2)*256+o]=v.z; w1T[(c+3)*256+o]=v.w;
    }
    int c = tid & 63, o4b = tid >> 6;
#pragma unroll
    for (int it = 0; it < 16; it++){
      int o2 = (o4b + 4*it) * 4;
      float4 v = *(const float4*)(w2 + c*256 + o2);
      w2T[o2*64+c]=v.x; w2T[(o2+1)*64+c]=v.y; w2T[(o2+2)*64+c]=v.z; w2T[(o2+3)*64+c]=v.w;
    }
  }
  if (tid < 64){
    float r = g_rs[tid] * g1[tid];
    ssc[tid] = r;
    ssh[tid] = b1[tid] - g_mu[tid]*r;
  }
  __syncthreads();

  int rowbase = blockIdx.x * 64;
  for (int it = 0; it < 16; it++){
    int row0 = rowbase + it*4;
    {
      int c = tid >> 2, j = tid & 3;
      sf1T[tid] = g_f0[(size_t)(row0+j)*CC + c]*ssc[c] + ssh[c];
    }
    __syncthreads();
    // layer 1: thread = o, 4 rows at once
    float h0=0.f,h1=0.f,h2=0.f,h3=0.f;
#pragma unroll
    for (int c = 0; c < 64; c++){
      float w = w1T[c*256 + tid];
      float4 f = *(const float4*)(sf1T + c*4);
      h0+=f.x*w; h1+=f.y*w; h2+=f.z*w; h3+=f.w*w;
    }
    h0 = (h0>0.f)?h0:0.2f*h0; h1 = (h1>0.f)?h1:0.2f*h1;
    h2 = (h2>0.f)?h2:0.2f*h2; h3 = (h3>0.f)?h3:0.2f*h3;
    *(float4*)(shT + tid*4) = make_float4(h0,h1,h2,h3);
    __syncthreads();
    // layer 2: c = tid&63, part = tid>>6
    {
      int c = tid & 63, part = tid >> 6;
      float p0=0.f,p1=0.f,p2=0.f,p3=0.f;
#pragma unroll
      for (int oo = 0; oo < 64; oo++){
        int o = part*64 + oo;
        float w = w2T[o*64 + c];
        float4 hv = *(const float4*)(shT + o*4);
        p0+=hv.x*w; p1+=hv.y*w; p2+=hv.z*w; p3+=hv.w*w;
      }
      spart[(0*4+part)*64 + c] = p0;
      spart[(1*4+part)*64 + c] = p1;
      spart[(2*4+part)*64 + c] = p2;
      spart[(3*4+part)*64 + c] = p3;
    }
    __syncthreads();
    {
      int c = tid & 63, j = tid >> 6;
      float ff = spart[(j*4+0)*64+c] + spart[(j*4+1)*64+c]
               + spart[(j*4+2)*64+c] + spart[(j*4+3)*64+c];
      g_f2[(size_t)(row0+j)*CC + c] = sf1T[c*4+j] + ff;
    }
    __syncthreads();
  }
}

// -------------------- 7. BN2-normalize + transpose to (B,C,N) --------------------
__global__ void out_kernel(const float* __restrict__ g2, const float* __restrict__ b2,
                           float* __restrict__ out){
  __shared__ float tile[32][33];
  int b  = blockIdx.z;
  int c0 = blockIdx.y * 32;
  int n0 = blockIdx.x * 32;
  int tx = threadIdx.x, ty = threadIdx.y;
  const float* fb = g_f2 + (size_t)b*NN*CC;
#pragma unroll
  for (int i = 0; i < 32; i += 8)
    tile[ty+i][tx] = fb[(size_t)(n0+ty+i)*CC + c0 + tx];
  __syncthreads();
#pragma unroll
  for (int i = 0; i < 32; i += 8){
    int c = c0 + ty + i;
    float sc = g_rs[c]*g2[c];
    float sh = b2[c] - g_mu[c]*sc;
    out[((size_t)b*CC + c)*NN + n0 + tx] = tile[tx][ty+i]*sc + sh;
  }
}

// -------------------- launch --------------------
extern "C" void kernel_launch(void* const* d_in, const int* in_sizes, int n_in,
                              void* d_out, int out_size){
  (void)in_sizes; (void)n_in; (void)out_size;
  const float* x  = (const float*)d_in[0];
  const float* wq = (const float*)d_in[1];
  const float* wk = (const float*)d_in[2];
  const float* wv = (const float*)d_in[3];
  const float* w1 = (const float*)d_in[4];
  const float* w2 = (const float*)d_in[5];
  const float* g1 = (const float*)d_in[6];
  const float* b1 = (const float*)d_in[7];
  const float* g2 = (const float*)d_in[8];
  const float* b2 = (const float*)d_in[9];
  float* out = (float*)d_out;

  const int ATTN_SMEM = (12288 + AT_WARPS*AT_WBUF) * 4;          // 221184 B
  const int MLP_SMEM  = (16384 + 16384 + 256 + 1024 + 1024) * 4; // 140288 B
  cudaFuncSetAttribute(attn_kernel, cudaFuncAttributeMaxDynamicSharedMemorySize, ATTN_SMEM);
  cudaFuncSetAttribute(mlp_kernel,  cudaFuncAttributeMaxDynamicSharedMemorySize, MLP_SMEM);

  transpose_kernel<<<dim3(NN/32, CC/32, BB), dim3(32,8)>>>(x);
  sqnorm_kernel<<<ROWS/256, 256>>>();
  knn_kernel<<<dim3(NN/32, BB), 256>>>();
  attn_kernel<<<ROWS/(AT_WARPS*4), 512, ATTN_SMEM>>>(wq, wk, wv);
  bn_stats_kernel<<<128, 256>>>(0);
  bn_finalize_kernel<<<1, 64>>>();
  mlp_kernel<<<ROWS/64, 256, MLP_SMEM>>>(w1, w2, g1, b1);
  bn_stats_kernel<<<128, 256>>>(1);
  bn_finalize_kernel<<<1, 64>>>();
  out_kernel<<<dim3(NN/32, CC/32, BB), dim3(32,8)>>>(g2, b2, out);
}

// round 3
// speedup vs baseline: 1.7781x; 1.1767x over previous
#include <cuda_runtime.h>
#include <cuda_bf16.h>
#include <float.h>

// Problem constants
#define BB 8
#define CC 64
#define NN 4096
#define KK 32
#define HH 4
#define DD 16
#define ROWS (BB*NN)          // 32768
#define FULLMASK 0xffffffffu

// -------------------- device scratch --------------------
__device__ float g_feat[ROWS*CC];   // (B,N,C) fp32
__device__ float g_sqn[ROWS];       // squared norms
__device__ int   g_knn[ROWS*KK];    // top-K indices (in-batch n)
__device__ float g_f0[ROWS*CC];     // feat + attention out
__device__ float g_f2[ROWS*CC];     // f1 + ff (pre-BN2)
__device__ float g_psum[128*CC];
__device__ float g_psq[128*CC];
__device__ float g_mu[CC];
__device__ float g_rs[CC];

// -------------------- warp helpers --------------------
__device__ __forceinline__ float warp_max32(float v){
#pragma unroll
  for (int o=16;o>0;o>>=1) v = fmaxf(v, __shfl_xor_sync(FULLMASK, v, o));
  return v;
}
__device__ __forceinline__ float warp_sum32(float v){
#pragma unroll
  for (int o=16;o>0;o>>=1) v += __shfl_xor_sync(FULLMASK, v, o);
  return v;
}

// packed f32x2 FMA (Blackwell native; ptxas won't auto-fuse)
__device__ __forceinline__ void ffma2(unsigned long long& d, unsigned long long a,
                                      unsigned long long b){
  asm("fma.rn.f32x2 %0, %1, %2, %0;" : "+l"(d) : "l"(a), "l"(b));
}
__device__ __forceinline__ float2 unpk(unsigned long long v){
  float2 r; asm("mov.b64 {%0, %1}, %2;" : "=f"(r.x), "=f"(r.y) : "l"(v));
  return r;
}
// order-preserving float->uint transform
__device__ __forceinline__ unsigned ofix(float v){
  unsigned u = __float_as_uint(v);
  return (u & 0x80000000u) ? ~u : (u | 0x80000000u);
}

// -------------------- 1. transpose x (B,C,N) -> feat (B,N,C) --------------------
__global__ void transpose_kernel(const float* __restrict__ x){
  __shared__ float tile[32][33];
  int b  = blockIdx.z;
  int c0 = blockIdx.y * 32;
  int n0 = blockIdx.x * 32;
  int tx = threadIdx.x, ty = threadIdx.y;   // (32,8)
  const float* xb = x + (size_t)b*CC*NN;
#pragma unroll
  for (int i = 0; i < 32; i += 8)
    tile[ty+i][tx] = xb[(size_t)(c0+ty+i)*NN + n0 + tx];
  __syncthreads();
  float* fb = g_feat + (size_t)b*NN*CC;
#pragma unroll
  for (int i = 0; i < 32; i += 8)
    fb[(size_t)(n0+ty+i)*CC + c0 + tx] = tile[tx][ty+i];
}

// -------------------- 2. squared norms --------------------
__global__ void sqnorm_kernel(){
  int row = blockIdx.x*blockDim.x + threadIdx.x;
  if (row >= ROWS) return;
  const float4* f = (const float4*)(g_feat + (size_t)row*CC);
  float s = 0.f;
#pragma unroll
  for (int i=0;i<16;i++){ float4 v=f[i]; s += v.x*v.x+v.y*v.y+v.z*v.z+v.w*v.w; }
  g_sqn[row] = s;
}

// -------------------- 3. KNN: f32x2 Gram + packed-argmin online top-32 ----------
// Block 256 thr = 8 warps. Block owns 64 rows (8/warp), streams m in tiles of 128.
__global__ __launch_bounds__(256) void knn_kernel(){
  __shared__ float2 fnT2[64][64];   // [c][r] duplicated {v,v} -> ready f32x2 bcast
  __shared__ float  fmT[64][128];   // [c][m]
  __shared__ float  ssq[128];
  int b = blockIdx.y;
  int nbase = blockIdx.x * 64;
  const float* fb = g_feat + (size_t)b*NN*CC;
  int tid = threadIdx.x;
  int lane = tid & 31, wid = tid >> 5;
  int r0 = wid * 8;

  // load fnT2 (64 rows) transposed + duplicated
  {
    int r = tid & 63, cg = tid >> 6;     // cg 0..3
#pragma unroll
    for (int it = 0; it < 4; it++){
      int c = (cg + it*4) * 4;
      float4 v = *(const float4*)(fb + (size_t)(nbase + r)*CC + c);
      fnT2[c  ][r] = make_float2(v.x, v.x);
      fnT2[c+1][r] = make_float2(v.y, v.y);
      fnT2[c+2][r] = make_float2(v.z, v.z);
      fnT2[c+3][r] = make_float2(v.w, v.w);
    }
  }

  // per-row state: packed cur values (order-fixed bits, low 5 = owning lane)
  unsigned cur_lo[8]; int cur_idx[8]; unsigned thr[8];
#pragma unroll
  for (int i=0;i<8;i++){ cur_lo[i] = (unsigned)lane; cur_idx[i] = 0; thr[i] = 0u; }

  for (int mbase = 0; mbase < NN; mbase += 128){
    __syncthreads();
    {
      int m = tid & 127; int cgb = tid >> 7;   // 0/1
#pragma unroll
      for (int it = 0; it < 8; it++){
        int c = (cgb + it*2) * 4;
        float4 v = *(const float4*)(fb + (size_t)(mbase + m)*CC + c);
        fmT[c][m]=v.x; fmT[c+1][m]=v.y; fmT[c+2][m]=v.z; fmT[c+3][m]=v.w;
      }
      if (tid < 128) ssq[tid] = g_sqn[(size_t)b*NN + mbase + tid];
    }
    __syncthreads();

    // 8 rows x 4 m per lane, packed as 8 x 2 f32x2 accumulators
    unsigned long long acc[8][2];
#pragma unroll
    for (int i=0;i<8;i++){ acc[i][0]=0ull; acc[i][1]=0ull; }

#pragma unroll 4
    for (int c = 0; c < 64; c++){
      const ulonglong2* fp = (const ulonglong2*)&fnT2[c][r0];
      ulonglong2 fA = fp[0], fB = fp[1], fC = fp[2], fD = fp[3];
      ulonglong2 mm = *(const ulonglong2*)&fmT[c][lane<<2];
      ffma2(acc[0][0], fA.x, mm.x); ffma2(acc[0][1], fA.x, mm.y);
      ffma2(acc[1][0], fA.y, mm.x); ffma2(acc[1][1], fA.y, mm.y);
      ffma2(acc[2][0], fB.x, mm.x); ffma2(acc[2][1], fB.x, mm.y);
      ffma2(acc[3][0], fB.y, mm.x); ffma2(acc[3][1], fB.y, mm.y);
      ffma2(acc[4][0], fC.x, mm.x); ffma2(acc[4][1], fC.x, mm.y);
      ffma2(acc[5][0], fC.y, mm.x); ffma2(acc[5][1], fC.y, mm.y);
      ffma2(acc[6][0], fD.x, mm.x); ffma2(acc[6][1], fD.x, mm.y);
      ffma2(acc[7][0], fD.y, mm.x); ffma2(acc[7][1], fD.y, mm.y);
    }

    float4 sq4 = *(const float4*)(&ssq[lane<<2]);
#pragma unroll
    for (int i=0;i<8;i++){
      float2 dA = unpk(acc[i][0]);
      float2 dB = unpk(acc[i][1]);
      unsigned u0 = ofix(fmaf(2.f, dA.x, -sq4.x));
      unsigned u1 = ofix(fmaf(2.f, dA.y, -sq4.y));
      unsigned u2 = ofix(fmaf(2.f, dB.x, -sq4.z));
      unsigned u3 = ofix(fmaf(2.f, dB.y, -sq4.w));
      unsigned um = max(max(u0,u1), max(u2,u3));
      if (!__any_sync(FULLMASK, um > thr[i])) continue;
      unsigned uu[4] = {u0,u1,u2,u3};
#pragma unroll
      for (int j=0;j<4;j++){
        unsigned cu = uu[j];
        int      ci = mbase + (lane<<2) + j;
        unsigned mask = __ballot_sync(FULLMASK, cu > thr[i]);
        while (mask){
          int src = __ffs(mask) - 1; mask &= mask - 1;
          unsigned c_u = __shfl_sync(FULLMASK, cu, src);
          int      c_i = __shfl_sync(FULLMASK, ci, src);
          // packed warp-min (value bits + lane in low 5)
          unsigned mp = cur_lo[i];
#pragma unroll
          for (int off=16; off>0; off>>=1)
            mp = min(mp, __shfl_xor_sync(FULLMASK, mp, off));
          if (c_u > mp){
            if (lane == (int)(mp & 31u)){ cur_lo[i] = (c_u & ~31u) | (unsigned)lane; cur_idx[i] = c_i; }
            thr[i] = mp;   // lazy lower bound (pre-insertion min)
          }
        }
      }
    }
  }
#pragma unroll
  for (int i=0;i<8;i++)
    g_knn[((size_t)b*NN + nbase + r0 + i)*KK + lane] = cur_idx[i];
}

// -------------------- 4. factorized attention --------------------
#define AT_WARPS 16
#define AT_WBUF 2688            // floats per warp
#define DIFF_LD 68              // padded row stride for diff [k][68]

__global__ __launch_bounds__(512) void attn_kernel(const float* __restrict__ wq,
                                                   const float* __restrict__ wk,
                                                   const float* __restrict__ wv){
  extern __shared__ float sm[];
  float2* wq2 = (float2*)sm;          // [c][o32] pairs (o, o+32)   2048 f2
  float2* wv2 = wq2 + 2048;           // [c][o32]                   2048 f2
  float2* wk2 = wv2 + 2048;           // [o][c32] pairs (c, c+32)   2048 f2
  int tid = threadIdx.x;
  int lane = tid & 31, wid = tid >> 5;
  float* wb    = sm + 12288 + wid*AT_WBUF;
  float* sdiff = wb;                  // [k][68]  2176
  float* sfn   = wb + 2176;           // 64
  float* sq    = wb + 2240;           // 64
  float* sqk   = wb + 2304;           // [h][64]  256 (reused as swd)
  float* sattn = wb + 2560;           // [k][4]   128
  float* swd   = sqk;

  for (int idx = tid; idx < 2048; idx += 512){
    int cc = idx >> 5, oo = idx & 31;
    wq2[idx] = make_float2(wq[oo*64 + cc], wq[(oo+32)*64 + cc]);
    wv2[idx] = make_float2(wv[oo*64 + cc], wv[(oo+32)*64 + cc]);
    int o = idx >> 5, c = idx & 31;
    wk2[idx] = make_float2(wk[o*64 + c], wk[o*64 + c + 32]);
  }
  __syncthreads();

  int rowbase = blockIdx.x * (AT_WARPS*4);

  for (int rr = 0; rr < 4; rr++){
    int row = rowbase + wid*4 + rr;
    int b = row >> 12;

    sfn[lane]      = g_feat[(size_t)row*CC + lane];
    sfn[lane + 32] = g_feat[(size_t)row*CC + lane + 32];
    __syncwarp();

    {
      int nbr = g_knn[(size_t)row*KK + lane];
      const float4* frow = (const float4*)(g_feat + ((size_t)(b<<12) + nbr)*CC);
      float4* drow = (float4*)(sdiff + lane*DIFF_LD);
#pragma unroll
      for (int c4 = 0; c4 < 16; c4++){
        float4 v = frow[c4];
        float4 f = *(const float4*)(sfn + c4*4);
        drow[c4] = make_float4(v.x-f.x, v.y-f.y, v.z-f.z, v.w-f.w);
      }
    }

    {
      float q0 = 0.f, q1 = 0.f;
#pragma unroll
      for (int c4 = 0; c4 < 16; c4++){
        float4 f = *(const float4*)(sfn + c4*4);
        float2 w0 = wq2[(c4*4  )*32 + lane];
        float2 w1 = wq2[(c4*4+1)*32 + lane];
        float2 w2 = wq2[(c4*4+2)*32 + lane];
        float2 w3 = wq2[(c4*4+3)*32 + lane];
        q0 += f.x*w0.x + f.y*w1.x + f.z*w2.x + f.w*w3.x;
        q1 += f.x*w0.y + f.y*w1.y + f.z*w2.y + f.w*w3.y;
      }
      sq[lane] = q0; sq[lane+32] = q1;
    }
    __syncwarp();

    {
      float a[8];
#pragma unroll
      for (int t=0;t<8;t++) a[t]=0.f;
#pragma unroll
      for (int o = 0; o < 64; o++){
        int h = o >> 4;
        float qb = sq[o];
        float2 w = wk2[o*32 + lane];
        a[h*2  ] += qb*w.x;
        a[h*2+1] += qb*w.y;
      }
#pragma unroll
      for (int h=0;h<4;h++){
        sqk[h*64 + lane]      = a[h*2];
        sqk[h*64 + lane + 32] = a[h*2+1];
      }
    }
    __syncwarp();

    {
      float e0=0.f,e1=0.f,e2=0.f,e3=0.f;
      const float4* drow = (const float4*)(sdiff + lane*DIFF_LD);
#pragma unroll
      for (int c4 = 0; c4 < 16; c4++){
        float4 d = drow[c4];
        float4 k0 = *(const float4*)(sqk + 0*64 + c4*4);
        float4 k1 = *(const float4*)(sqk + 1*64 + c4*4);
        float4 k2 = *(const float4*)(sqk + 2*64 + c4*4);
        float4 k3 = *(const float4*)(sqk + 3*64 + c4*4);
        e0 += d.x*k0.x + d.y*k0.y + d.z*k0.z + d.w*k0.w;
        e1 += d.x*k1.x + d.y*k1.y + d.z*k1.z + d.w*k1.w;
        e2 += d.x*k2.x + d.y*k2.y + d.z*k2.z + d.w*k2.w;
        e3 += d.x*k3.x + d.y*k3.y + d.z*k3.z + d.w*k3.w;
      }
      float e[4] = {e0*0.25f, e1*0.25f, e2*0.25f, e3*0.25f};
      float a[4];
#pragma unroll
      for (int h=0;h<4;h++){
        float mx = warp_max32(e[h]);
        float ex = __expf(e[h]-mx);
        float s  = warp_sum32(ex);
        a[h] = ex / s;
      }
      *(float4*)(sattn + lane*4) = make_float4(a[0],a[1],a[2],a[3]);
    }
    __syncwarp();

    {
      float w[8];
#pragma unroll
      for (int t=0;t<8;t++) w[t]=0.f;
#pragma unroll
      for (int k = 0; k < 32; k++){
        float4 at = *(const float4*)(sattn + k*4);
        float d0 = sdiff[k*DIFF_LD + lane];
        float d1 = sdiff[k*DIFF_LD + lane + 32];
        w[0]+=at.x*d0; w[1]+=at.x*d1;
        w[2]+=at.y*d0; w[3]+=at.y*d1;
        w[4]+=at.z*d0; w[5]+=at.z*d1;
        w[6]+=at.w*d0; w[7]+=at.w*d1;
      }
      __syncwarp();
#pragma unroll
      for (int h=0;h<4;h++){
        swd[h*64 + lane]      = w[h*2];
        swd[h*64 + lane + 32] = w[h*2+1];
      }
    }
    __syncwarp();

    {
      int h0 = lane >> 4;
      float o0 = 0.f, o1 = 0.f;
#pragma unroll
      for (int c4 = 0; c4 < 16; c4++){
        float4 d0 = *(const float4*)(swd + h0*64     + c4*4);
        float4 d1 = *(const float4*)(swd + (h0+2)*64 + c4*4);
        float2 w0 = wv2[(c4*4  )*32 + lane];
        float2 w1 = wv2[(c4*4+1)*32 + lane];
        float2 w2 = wv2[(c4*4+2)*32 + lane];
        float2 w3 = wv2[(c4*4+3)*32 + lane];
        o0 += d0.x*w0.x + d0.y*w1.x + d0.z*w2.x + d0.w*w3.x;
        o1 += d1.x*w0.y + d1.y*w1.y + d1.z*w2.y + d1.w*w3.y;
      }
      g_f0[(size_t)row*CC + lane]      = sfn[lane]      + o0;
      g_f0[(size_t)row*CC + lane + 32] = sfn[lane + 32] + o1;
    }
    __syncwarp();
  }
}

// -------------------- 5. BN stats (deterministic two-stage) --------------------
__global__ __launch_bounds__(256) void bn_stats_kernel(int which){
  const float* f = which ? g_f2 : g_f0;
  __shared__ float s1[256], s2[256];
  int c = threadIdx.x & 63, g = threadIdx.x >> 6;
  int rowbase = blockIdx.x * 256;
  float s = 0.f, q = 0.f;
  for (int r = g; r < 256; r += 4){
    float v = f[(size_t)(rowbase + r)*CC + c];
    s += v; q += v*v;
  }
  s1[threadIdx.x] = s; s2[threadIdx.x] = q;
  __syncthreads();
  if (threadIdx.x < 64){
    s = s1[c] + s1[c+64] + s1[c+128] + s1[c+192];
    q = s2[c] + s2[c+64] + s2[c+128] + s2[c+192];
    g_psum[blockIdx.x*64 + c] = s;
    g_psq [blockIdx.x*64 + c] = q;
  }
}

__global__ void bn_finalize_kernel(){
  int c = threadIdx.x;  // 64 threads
  float s = 0.f, q = 0.f;
  for (int i = 0; i < 128; i++){ s += g_psum[i*64 + c]; q += g_psq[i*64 + c]; }
  float m   = s * (1.f/32768.f);
  float var = q * (1.f/32768.f) - m*m;
  g_mu[c] = m;
  g_rs[c] = rsqrtf(var + 1e-5f);
}

// -------------------- 6. BN1-normalize + MLP + residual (4 rows/iter) ------------
__global__ __launch_bounds__(256) void mlp_kernel(const float* __restrict__ w1,
                                                  const float* __restrict__ w2,
                                                  const float* __restrict__ g1,
                                                  const float* __restrict__ b1){
  extern __shared__ float sm[];
  float* w1T   = sm;              // [c][o] 64x256
  float* w2T   = sm + 16384;      // [o][c] 256x64
  float* sf1T  = sm + 32768;      // [c][j] 64x4
  float* shT   = sm + 33024;      // [o][j] 256x4
  float* spart = sm + 34048;      // [(j*4+part)][c] 16x64
  __shared__ float ssc[64], ssh[64];
  int tid = threadIdx.x;

  {
    int o = tid;
#pragma unroll
    for (int c4 = 0; c4 < 16; c4++){
      float4 v = *(const float4*)(w1 + o*64 + c4*4);
      int c = c4*4;
      w1T[c*256+o]=v.x; w1T[(c+1)*256+o]=v.y; w1T[(c+2)*256+o]=v.z; w1T[(c+3)*256+o]=v.w;
    }
    int c = tid & 63, o4b = tid >> 6;
#pragma unroll
    for (int it = 0; it < 16; it++){
      int o2 = (o4b + 4*it) * 4;
      float4 v = *(const float4*)(w2 + c*256 + o2);
      w2T[o2*64+c]=v.x; w2T[(o2+1)*64+c]=v.y; w2T[(o2+2)*64+c]=v.z; w2T[(o2+3)*64+c]=v.w;
    }
  }
  if (tid < 64){
    float r = g_rs[tid] * g1[tid];
    ssc[tid] = r;
    ssh[tid] = b1[tid] - g_mu[tid]*r;
  }
  __syncthreads();

  int rowbase = blockIdx.x * 64;
  for (int it = 0; it < 16; it++){
    int row0 = rowbase + it*4;
    {
      int c = tid >> 2, j = tid & 3;
      sf1T[tid] = g_f0[(size_t)(row0+j)*CC + c]*ssc[c] + ssh[c];
    }
    __syncthreads();
    float h0=0.f,h1=0.f,h2=0.f,h3=0.f;
#pragma unroll
    for (int c = 0; c < 64; c++){
      float w = w1T[c*256 + tid];
      float4 f = *(const float4*)(sf1T + c*4);
      h0+=f.x*w; h1+=f.y*w; h2+=f.z*w; h3+=f.w*w;
    }
    h0 = (h0>0.f)?h0:0.2f*h0; h1 = (h1>0.f)?h1:0.2f*h1;
    h2 = (h2>0.f)?h2:0.2f*h2; h3 = (h3>0.f)?h3:0.2f*h3;
    *(float4*)(shT + tid*4) = make_float4(h0,h1,h2,h3);
    __syncthreads();
    {
      int c = tid & 63, part = tid >> 6;
      float p0=0.f,p1=0.f,p2=0.f,p3=0.f;
#pragma unroll
      for (int oo = 0; oo < 64; oo++){
        int o = part*64 + oo;
        float w = w2T[o*64 + c];
        float4 hv = *(const float4*)(shT + o*4);
        p0+=hv.x*w; p1+=hv.y*w; p2+=hv.z*w; p3+=hv.w*w;
      }
      spart[(0*4+part)*64 + c] = p0;
      spart[(1*4+part)*64 + c] = p1;
      spart[(2*4+part)*64 + c] = p2;
      spart[(3*4+part)*64 + c] = p3;
    }
    __syncthreads();
    {
      int c = tid & 63, j = tid >> 6;
      float ff = spart[(j*4+0)*64+c] + spart[(j*4+1)*64+c]
               + spart[(j*4+2)*64+c] + spart[(j*4+3)*64+c];
      g_f2[(size_t)(row0+j)*CC + c] = sf1T[c*4+j] + ff;
    }
    __syncthreads();
  }
}

// -------------------- 7. BN2-normalize + transpose to (B,C,N) --------------------
__global__ void out_kernel(const float* __restrict__ g2, const float* __restrict__ b2,
                           float* __restrict__ out){
  __shared__ float tile[32][33];
  int b  = blockIdx.z;
  int c0 = blockIdx.y * 32;
  int n0 = blockIdx.x * 32;
  int tx = threadIdx.x, ty = threadIdx.y;
  const float* fb = g_f2 + (size_t)b*NN*CC;
#pragma unroll
  for (int i = 0; i < 32; i += 8)
    tile[ty+i][tx] = fb[(size_t)(n0+ty+i)*CC + c0 + tx];
  __syncthreads();
#pragma unroll
  for (int i = 0; i < 32; i += 8){
    int c = c0 + ty + i;
    float sc = g_rs[c]*g2[c];
    float sh = b2[c] - g_mu[c]*sc;
    out[((size_t)b*CC + c)*NN + n0 + tx] = tile[tx][ty+i]*sc + sh;
  }
}

// -------------------- launch --------------------
extern "C" void kernel_launch(void* const* d_in, const int* in_sizes, int n_in,
                              void* d_out, int out_size){
  (void)in_sizes; (void)n_in; (void)out_size;
  const float* x  = (const float*)d_in[0];
  const float* wq = (const float*)d_in[1];
  const float* wk = (const float*)d_in[2];
  const float* wv = (const float*)d_in[3];
  const float* w1 = (const float*)d_in[4];
  const float* w2 = (const float*)d_in[5];
  const float* g1 = (const float*)d_in[6];
  const float* b1 = (const float*)d_in[7];
  const float* g2 = (const float*)d_in[8];
  const float* b2 = (const float*)d_in[9];
  float* out = (float*)d_out;

  const int ATTN_SMEM = (12288 + AT_WARPS*AT_WBUF) * 4;          // 221184 B
  const int MLP_SMEM  = (16384 + 16384 + 256 + 1024 + 1024) * 4; // 140288 B
  cudaFuncSetAttribute(attn_kernel, cudaFuncAttributeMaxDynamicSharedMemorySize, ATTN_SMEM);
  cudaFuncSetAttribute(mlp_kernel,  cudaFuncAttributeMaxDynamicSharedMemorySize, MLP_SMEM);

  transpose_kernel<<<dim3(NN/32, CC/32, BB), dim3(32,8)>>>(x);
  sqnorm_kernel<<<ROWS/256, 256>>>();
  knn_kernel<<<dim3(NN/64, BB), 256>>>();
  attn_kernel<<<ROWS/(AT_WARPS*4), 512, ATTN_SMEM>>>(wq, wk, wv);
  bn_stats_kernel<<<128, 256>>>(0);
  bn_finalize_kernel<<<1, 64>>>();
  mlp_kernel<<<ROWS/64, 256, MLP_SMEM>>>(w1, w2, g1, b1);
  bn_stats_kernel<<<128, 256>>>(1);
  bn_finalize_kernel<<<1, 64>>>();
  out_kernel<<<dim3(NN/32, CC/32, BB), dim3(32,8)>>>(g2, b2, out);
}